// round 1
// baseline (speedup 1.0000x reference)
#include <cuda_runtime.h>
#include <math.h>

// Global accumulators (no device allocation allowed).
__device__ double g_sum_d;
__device__ double g_sum_d2;
__device__ double g_sum_p;

#define NTHREADS 256
#define NWARPS   (NTHREADS / 32)

__global__ void afl_zero_kernel() {
    g_sum_d  = 0.0;
    g_sum_d2 = 0.0;
    g_sum_p  = 0.0;
}

__device__ __forceinline__ float warp_reduce_f(float v) {
    #pragma unroll
    for (int o = 16; o > 0; o >>= 1)
        v += __shfl_xor_sync(0xFFFFFFFFu, v, o);
    return v;
}

// Pass 1: sum of d and d^2,  d = |pred - target|
__global__ void afl_pass1_kernel(const float* __restrict__ pred,
                                 const float* __restrict__ target,
                                 long long n) {
    long long n4 = n >> 2;
    const float4* p4 = (const float4*)pred;
    const float4* t4 = (const float4*)target;

    float sd = 0.0f, sd2 = 0.0f;
    long long stride = (long long)gridDim.x * blockDim.x;
    for (long long i = (long long)blockIdx.x * blockDim.x + threadIdx.x; i < n4; i += stride) {
        float4 a = p4[i];
        float4 b = t4[i];
        float d0 = fabsf(a.x - b.x);
        float d1 = fabsf(a.y - b.y);
        float d2 = fabsf(a.z - b.z);
        float d3 = fabsf(a.w - b.w);
        sd  += (d0 + d1) + (d2 + d3);
        sd2 += fmaf(d0, d0, d1 * d1) + fmaf(d2, d2, d3 * d3);
    }
    // scalar tail
    for (long long i = (n4 << 2) + (long long)blockIdx.x * blockDim.x + threadIdx.x;
         i < n; i += stride) {
        float d = fabsf(pred[i] - target[i]);
        sd += d; sd2 += d * d;
    }

    sd  = warp_reduce_f(sd);
    sd2 = warp_reduce_f(sd2);

    __shared__ double shA[NWARPS];
    __shared__ double shB[NWARPS];
    int lane = threadIdx.x & 31;
    int wid  = threadIdx.x >> 5;
    if (lane == 0) { shA[wid] = (double)sd; shB[wid] = (double)sd2; }
    __syncthreads();
    if (wid == 0) {
        double a = (lane < NWARPS) ? shA[lane] : 0.0;
        double b = (lane < NWARPS) ? shB[lane] : 0.0;
        #pragma unroll
        for (int o = 16; o > 0; o >>= 1) {
            a += __shfl_xor_sync(0xFFFFFFFFu, a, o);
            b += __shfl_xor_sync(0xFFFFFFFFu, b, o);
        }
        if (lane == 0) {
            atomicAdd(&g_sum_d,  a);
            atomicAdd(&g_sum_d2, b);
        }
    }
}

// Pass 2: sum of (1 - erf(d / var * INV_SQRT2)); var read from pass-1 results.
__global__ void afl_pass2_kernel(const float* __restrict__ pred,
                                 const float* __restrict__ target,
                                 long long n) {
    // Each block recomputes var from the finished pass-1 sums (cheap, uniform).
    double sd  = g_sum_d;
    double sd2 = g_sum_d2;
    double dn  = (double)n;
    double var = (sd2 - sd * sd / dn) / (dn - 1.0);
    float  c   = (float)(0.7071067811865476 / var);

    long long n4 = n >> 2;
    const float4* p4 = (const float4*)pred;
    const float4* t4 = (const float4*)target;

    float sp = 0.0f;
    long long stride = (long long)gridDim.x * blockDim.x;
    for (long long i = (long long)blockIdx.x * blockDim.x + threadIdx.x; i < n4; i += stride) {
        float4 a = p4[i];
        float4 b = t4[i];
        float d0 = fabsf(a.x - b.x);
        float d1 = fabsf(a.y - b.y);
        float d2 = fabsf(a.z - b.z);
        float d3 = fabsf(a.w - b.w);
        sp += (1.0f - erff(d0 * c)) + (1.0f - erff(d1 * c));
        sp += (1.0f - erff(d2 * c)) + (1.0f - erff(d3 * c));
    }
    for (long long i = (n4 << 2) + (long long)blockIdx.x * blockDim.x + threadIdx.x;
         i < n; i += stride) {
        float d = fabsf(pred[i] - target[i]);
        sp += 1.0f - erff(d * c);
    }

    sp = warp_reduce_f(sp);

    __shared__ double shA[NWARPS];
    int lane = threadIdx.x & 31;
    int wid  = threadIdx.x >> 5;
    if (lane == 0) shA[wid] = (double)sp;
    __syncthreads();
    if (wid == 0) {
        double a = (lane < NWARPS) ? shA[lane] : 0.0;
        #pragma unroll
        for (int o = 16; o > 0; o >>= 1)
            a += __shfl_xor_sync(0xFFFFFFFFu, a, o);
        if (lane == 0) atomicAdd(&g_sum_p, a);
    }
}

__global__ void afl_finalize_kernel(float* __restrict__ out, long long n) {
    double dn     = (double)n;
    double sd     = g_sum_d;
    double sd2    = g_sum_d2;
    double mean_d = sd / dn;
    double var    = (sd2 - sd * sd / dn) / (dn - 1.0);
    double p      = g_sum_p / dn;
    double gamma  = -log(p);
    double loss   = mean_d * pow(1.0 - p, gamma) + log(var + 1.0);
    out[0] = (float)loss;  // LOSS_WEIGHT = 1.0
}

extern "C" void kernel_launch(void* const* d_in, const int* in_sizes, int n_in,
                              void* d_out, int out_size) {
    const float* pred   = (const float*)d_in[0];
    const float* target = (const float*)d_in[1];
    float* out = (float*)d_out;
    long long n = (long long)in_sizes[0];

    int blocks = 148 * 16;  // memory-bound grid; ~7 float4s per thread

    afl_zero_kernel<<<1, 1>>>();
    afl_pass1_kernel<<<blocks, NTHREADS>>>(pred, target, n);
    afl_pass2_kernel<<<blocks, NTHREADS>>>(pred, target, n);
    afl_finalize_kernel<<<1, 1>>>(out, n);
}

// round 3
// speedup vs baseline: 1.0995x; 1.0995x over previous
#include <cuda_runtime.h>
#include <cuda_fp16.h>
#include <math.h>

// ---- persistent device state (no allocations allowed) ----
#define CAP_ELEMS (1 << 24)            // 16,777,216 halves = 32 MiB
__device__ __half  g_dcache[CAP_ELEMS];
__device__ double  g_sum_d;            // zero-initialized at module load;
__device__ double  g_sum_d2;           // reset by finalize after each use.
__device__ double  g_sum_p;

#define NTHREADS 256
#define NWARPS   (NTHREADS / 32)
#define NBLOCKS  2048

// 8-byte vector of 4 halves
struct __align__(8) h2x2 { __half2 a, b; };

__device__ __forceinline__ float warp_reduce_f(float v) {
    #pragma unroll
    for (int o = 16; o > 0; o >>= 1)
        v += __shfl_xor_sync(0xFFFFFFFFu, v, o);
    return v;
}

__device__ __forceinline__ void block_reduce_2(float sd, float sd2,
                                               double* out_a, double* out_b) {
    sd  = warp_reduce_f(sd);
    sd2 = warp_reduce_f(sd2);
    __shared__ double shA[NWARPS];
    __shared__ double shB[NWARPS];
    int lane = threadIdx.x & 31;
    int wid  = threadIdx.x >> 5;
    if (lane == 0) { shA[wid] = (double)sd; shB[wid] = (double)sd2; }
    __syncthreads();
    if (wid == 0) {
        double a = (lane < NWARPS) ? shA[lane] : 0.0;
        double b = (lane < NWARPS) ? shB[lane] : 0.0;
        #pragma unroll
        for (int o = 4; o > 0; o >>= 1) {
            a += __shfl_xor_sync(0xFFFFFFFFu, a, o);
            b += __shfl_xor_sync(0xFFFFFFFFu, b, o);
        }
        if (lane == 0) { atomicAdd(out_a, a); atomicAdd(out_b, b); }
    }
}

__device__ __forceinline__ void block_reduce_1(float s, double* out) {
    s = warp_reduce_f(s);
    __shared__ double shA[NWARPS];
    int lane = threadIdx.x & 31;
    int wid  = threadIdx.x >> 5;
    if (lane == 0) shA[wid] = (double)s;
    __syncthreads();
    if (wid == 0) {
        double a = (lane < NWARPS) ? shA[lane] : 0.0;
        #pragma unroll
        for (int o = 4; o > 0; o >>= 1)
            a += __shfl_xor_sync(0xFFFFFFFFu, a, o);
        if (lane == 0) atomicAdd(out, a);
    }
}

// ---- pass 1: sum d, sum d^2; optionally cache d as fp16 ----
template <bool STORE>
__global__ void afl_pass1_kernel(const float* __restrict__ pred,
                                 const float* __restrict__ target,
                                 long long n) {
    const long long n4 = n >> 2;
    const float4* __restrict__ p4 = (const float4*)pred;
    const float4* __restrict__ t4 = (const float4*)target;
    h2x2* __restrict__ cache4 = (h2x2*)g_dcache;   // 4 halves per entry

    const long long stride = (long long)gridDim.x * blockDim.x;
    long long i = (long long)blockIdx.x * blockDim.x + threadIdx.x;

    float sd = 0.0f, sd2 = 0.0f;

    // unroll-by-4 main: 8 front-batched LDG.128s per batch
    for (; i + 3 * stride < n4; i += 4 * stride) {
        float4 a0 = p4[i];
        float4 a1 = p4[i + stride];
        float4 a2 = p4[i + 2 * stride];
        float4 a3 = p4[i + 3 * stride];
        float4 b0 = t4[i];
        float4 b1 = t4[i + stride];
        float4 b2 = t4[i + 2 * stride];
        float4 b3 = t4[i + 3 * stride];
        #pragma unroll
        for (int u = 0; u < 4; u++) {
            float4 a = (u == 0) ? a0 : (u == 1) ? a1 : (u == 2) ? a2 : a3;
            float4 b = (u == 0) ? b0 : (u == 1) ? b1 : (u == 2) ? b2 : b3;
            float d0 = fabsf(a.x - b.x);
            float d1 = fabsf(a.y - b.y);
            float d2 = fabsf(a.z - b.z);
            float d3 = fabsf(a.w - b.w);
            sd  += (d0 + d1) + (d2 + d3);
            sd2 += fmaf(d0, d0, d1 * d1) + fmaf(d2, d2, d3 * d3);
            if (STORE) {
                h2x2 pk;
                pk.a = __floats2half2_rn(d0, d1);
                pk.b = __floats2half2_rn(d2, d3);
                cache4[i + (long long)u * stride] = pk;
            }
        }
    }
    // remainder float4s
    for (; i < n4; i += stride) {
        float4 a = p4[i];
        float4 b = t4[i];
        float d0 = fabsf(a.x - b.x);
        float d1 = fabsf(a.y - b.y);
        float d2 = fabsf(a.z - b.z);
        float d3 = fabsf(a.w - b.w);
        sd  += (d0 + d1) + (d2 + d3);
        sd2 += fmaf(d0, d0, d1 * d1) + fmaf(d2, d2, d3 * d3);
        if (STORE) {
            h2x2 pk;
            pk.a = __floats2half2_rn(d0, d1);
            pk.b = __floats2half2_rn(d2, d3);
            cache4[i] = pk;
        }
    }
    // scalar tail (n % 4)
    for (long long j = (n4 << 2) + (long long)blockIdx.x * blockDim.x + threadIdx.x;
         j < n; j += stride) {
        float d = fabsf(pred[j] - target[j]);
        sd += d; sd2 += d * d;
        if (STORE) g_dcache[j] = __float2half_rn(d);
    }

    block_reduce_2(sd, sd2, &g_sum_d, &g_sum_d2);
}

// ---- pass 2 (cached): read fp16 d, sum (1 - erf(d * c)) ----
__global__ void afl_pass2_cached_kernel(long long n) {
    double sd  = g_sum_d;
    double sd2 = g_sum_d2;
    double dn  = (double)n;
    double var = (sd2 - sd * sd / dn) / (dn - 1.0);
    float  c   = (float)(0.7071067811865476 / var);

    const long long n4 = n >> 2;
    const h2x2* __restrict__ cache4 = (const h2x2*)g_dcache;

    const long long stride = (long long)gridDim.x * blockDim.x;
    long long i = (long long)blockIdx.x * blockDim.x + threadIdx.x;

    float sp = 0.0f;
    for (; i + 3 * stride < n4; i += 4 * stride) {
        h2x2 q0 = cache4[i];
        h2x2 q1 = cache4[i + stride];
        h2x2 q2 = cache4[i + 2 * stride];
        h2x2 q3 = cache4[i + 3 * stride];
        #pragma unroll
        for (int u = 0; u < 4; u++) {
            h2x2 q = (u == 0) ? q0 : (u == 1) ? q1 : (u == 2) ? q2 : q3;
            float2 f0 = __half22float2(q.a);
            float2 f1 = __half22float2(q.b);
            sp += (1.0f - erff(f0.x * c)) + (1.0f - erff(f0.y * c));
            sp += (1.0f - erff(f1.x * c)) + (1.0f - erff(f1.y * c));
        }
    }
    for (; i < n4; i += stride) {
        h2x2 q = cache4[i];
        float2 f0 = __half22float2(q.a);
        float2 f1 = __half22float2(q.b);
        sp += (1.0f - erff(f0.x * c)) + (1.0f - erff(f0.y * c));
        sp += (1.0f - erff(f1.x * c)) + (1.0f - erff(f1.y * c));
    }
    for (long long j = (n4 << 2) + (long long)blockIdx.x * blockDim.x + threadIdx.x;
         j < n; j += stride) {
        sp += 1.0f - erff(__half2float(g_dcache[j]) * c);
    }

    block_reduce_1(sp, &g_sum_p);
}

// ---- pass 2 (direct, fallback for n > CAP_ELEMS) ----
__global__ void afl_pass2_direct_kernel(const float* __restrict__ pred,
                                        const float* __restrict__ target,
                                        long long n) {
    double sd  = g_sum_d;
    double sd2 = g_sum_d2;
    double dn  = (double)n;
    double var = (sd2 - sd * sd / dn) / (dn - 1.0);
    float  c   = (float)(0.7071067811865476 / var);

    const long long n4 = n >> 2;
    const float4* __restrict__ p4 = (const float4*)pred;
    const float4* __restrict__ t4 = (const float4*)target;

    const long long stride = (long long)gridDim.x * blockDim.x;
    long long i = (long long)blockIdx.x * blockDim.x + threadIdx.x;

    float sp = 0.0f;
    for (; i < n4; i += stride) {
        float4 a = p4[i];
        float4 b = t4[i];
        sp += (1.0f - erff(fabsf(a.x - b.x) * c)) + (1.0f - erff(fabsf(a.y - b.y) * c));
        sp += (1.0f - erff(fabsf(a.z - b.z) * c)) + (1.0f - erff(fabsf(a.w - b.w) * c));
    }
    for (long long j = (n4 << 2) + (long long)blockIdx.x * blockDim.x + threadIdx.x;
         j < n; j += stride) {
        sp += 1.0f - erff(fabsf(pred[j] - target[j]) * c);
    }
    block_reduce_1(sp, &g_sum_p);
}

// ---- finalize: float transcendentals; resets accumulators for next replay ----
__global__ void afl_finalize_kernel(float* __restrict__ out, long long n) {
    double dn     = (double)n;
    double sd     = g_sum_d;
    double sd2    = g_sum_d2;
    double mean_d = sd / dn;
    double var    = (sd2 - sd * sd / dn) / (dn - 1.0);
    float  p      = (float)(g_sum_p / dn);
    float  gamma  = -logf(p);
    // (1-p)^gamma = exp(gamma * log1p(-p))
    float  pw     = expf(gamma * log1pf(-p));
    float  loss   = (float)mean_d * pw + log1pf((float)var);
    out[0] = loss;  // LOSS_WEIGHT = 1.0

    // reset for next graph replay (globals start zeroed at module load)
    g_sum_d  = 0.0;
    g_sum_d2 = 0.0;
    g_sum_p  = 0.0;
}

extern "C" void kernel_launch(void* const* d_in, const int* in_sizes, int n_in,
                              void* d_out, int out_size) {
    const float* pred   = (const float*)d_in[0];
    const float* target = (const float*)d_in[1];
    float* out = (float*)d_out;
    long long n = (long long)in_sizes[0];

    if (n <= (long long)CAP_ELEMS) {
        afl_pass1_kernel<true><<<NBLOCKS, NTHREADS>>>(pred, target, n);
        afl_pass2_cached_kernel<<<NBLOCKS, NTHREADS>>>(n);
    } else {
        afl_pass1_kernel<false><<<NBLOCKS, NTHREADS>>>(pred, target, n);
        afl_pass2_direct_kernel<<<NBLOCKS, NTHREADS>>>(pred, target, n);
    }
    afl_finalize_kernel<<<1, 1>>>(out, n);
}

// round 4
// speedup vs baseline: 1.4332x; 1.3035x over previous
#include <cuda_runtime.h>
#include <cuda_fp16.h>
#include <math.h>

// ---- persistent device state (no allocations allowed) ----
__device__ double   g_sum_d;    // zero at module load; reset each launch by finalizer
__device__ double   g_sum_d2;
__device__ double   g_sum_p;
__device__ unsigned g_count;    // grid-barrier arrive counter (reset by last arriver)
__device__ unsigned g_gen;      // grid-barrier generation (monotonic across replays)

#define NBLK   148
#define NTHR   1024
#define NWARPS (NTHR / 32)

// fallback config
#define FB_BLOCKS  2048
#define FB_THREADS 256
#define FB_WARPS   (FB_THREADS / 32)

struct __align__(8) h2x2 { __half2 a, b; };

__device__ __forceinline__ float warp_reduce_f(float v) {
    #pragma unroll
    for (int o = 16; o > 0; o >>= 1)
        v += __shfl_xor_sync(0xFFFFFFFFu, v, o);
    return v;
}

// 1 - erf(x) for x >= 0. Abramowitz & Stegun 7.1.26, |abs err| <= 1.5e-7.
// Branchless: 1 fast-div (MUFU.RCP), 1 __expf (MUFU.EX2), ~7 FMA.
__device__ __forceinline__ float one_minus_erf(float x) {
    float t = __fdividef(1.0f, fmaf(0.3275911f, x, 1.0f));
    float poly = fmaf(t, 1.061405429f, -1.453152027f);
    poly = fmaf(poly, t, 1.421413741f);
    poly = fmaf(poly, t, -0.284496736f);
    poly = fmaf(poly, t, 0.254829592f);
    poly *= t;
    return poly * __expf(-x * x);
}

template <int WARPS>
__device__ __forceinline__ void block_reduce_2(float sd, float sd2,
                                               double* out_a, double* out_b) {
    sd  = warp_reduce_f(sd);
    sd2 = warp_reduce_f(sd2);
    __shared__ double shA[WARPS];
    __shared__ double shB[WARPS];
    int lane = threadIdx.x & 31;
    int wid  = threadIdx.x >> 5;
    if (lane == 0) { shA[wid] = (double)sd; shB[wid] = (double)sd2; }
    __syncthreads();
    if (wid == 0) {
        double a = (lane < WARPS) ? shA[lane] : 0.0;
        double b = (lane < WARPS) ? shB[lane] : 0.0;
        #pragma unroll
        for (int o = 16; o > 0; o >>= 1) {
            a += __shfl_xor_sync(0xFFFFFFFFu, a, o);
            b += __shfl_xor_sync(0xFFFFFFFFu, b, o);
        }
        if (lane == 0) { atomicAdd(out_a, a); atomicAdd(out_b, b); }
    }
    __syncthreads();   // shA/shB reused later; also keeps block together
}

template <int WARPS>
__device__ __forceinline__ void block_reduce_1(float s, double* out) {
    s = warp_reduce_f(s);
    __shared__ double shC[WARPS];
    int lane = threadIdx.x & 31;
    int wid  = threadIdx.x >> 5;
    if (lane == 0) shC[wid] = (double)s;
    __syncthreads();
    if (wid == 0) {
        double a = (lane < WARPS) ? shC[lane] : 0.0;
        #pragma unroll
        for (int o = 16; o > 0; o >>= 1)
            a += __shfl_xor_sync(0xFFFFFFFFu, a, o);
        if (lane == 0) atomicAdd(out, a);
    }
}

// Sense-reversing grid barrier. All blocks co-resident (grid = 148 <= #SMs,
// one block per SM by construction). Generation counter is monotonic, so the
// barrier works across graph replays without host-side resets.
__device__ __forceinline__ void grid_barrier(unsigned nblocks) {
    __syncthreads();
    if (threadIdx.x == 0) {
        unsigned gen = *((volatile unsigned*)&g_gen);
        __threadfence();
        unsigned arrived = atomicAdd(&g_count, 1u);
        if (arrived == nblocks - 1) {
            g_count = 0;            // safe: everyone has arrived; nobody spins on count
            __threadfence();
            atomicAdd(&g_gen, 1u);  // release
        } else {
            while (*((volatile unsigned*)&g_gen) == gen) { }
            __threadfence();        // acquire
        }
    }
    __syncthreads();
}

// ============================ fused persistent kernel =======================
extern __shared__ __half s_d[];   // this block's chunk of d values (fp16)

__global__ __launch_bounds__(NTHR, 1)
void afl_fused_kernel(const float* __restrict__ pred,
                      const float* __restrict__ target,
                      float* __restrict__ out,
                      long long n, long long chunk /* multiple of 4 */) {
    const int tid = threadIdx.x;
    const int bid = blockIdx.x;

    long long bstart = (long long)bid * chunk;
    if (bstart > n) bstart = n;
    long long bend = bstart + chunk;
    if (bend > n) bend = n;

    const long long b4s = bstart >> 2;      // bstart is multiple of 4
    const long long b4e = bend >> 2;        // floor; tail (<4) handled scalar

    const float4* __restrict__ p4 = (const float4*)pred;
    const float4* __restrict__ t4 = (const float4*)target;
    h2x2* __restrict__ s4 = (h2x2*)s_d;

    // ---------------- pass 1: sum d, sum d^2; stage d in SMEM ----------------
    float sd = 0.0f, sd2 = 0.0f;
    for (long long i = b4s + tid; i < b4e; i += NTHR) {
        float4 a = p4[i];
        float4 b = t4[i];
        float d0 = fabsf(a.x - b.x);
        float d1 = fabsf(a.y - b.y);
        float d2 = fabsf(a.z - b.z);
        float d3 = fabsf(a.w - b.w);
        sd  += (d0 + d1) + (d2 + d3);
        sd2 += fmaf(d0, d0, d1 * d1) + fmaf(d2, d2, d3 * d3);
        h2x2 pk;
        pk.a = __floats2half2_rn(d0, d1);
        pk.b = __floats2half2_rn(d2, d3);
        s4[i - b4s] = pk;
    }
    // scalar tail (only if bend % 4 != 0)
    for (long long j = (b4e << 2) + tid; j < bend; j += NTHR) {
        float d = fabsf(pred[j] - target[j]);
        sd += d; sd2 += d * d;
        s_d[j - bstart] = __float2half_rn(d);
    }

    block_reduce_2<NWARPS>(sd, sd2, &g_sum_d, &g_sum_d2);
    __threadfence();
    grid_barrier(gridDim.x);

    // ---------------- between passes: everyone computes var ------------------
    const double sdt  = g_sum_d;
    const double sd2t = g_sum_d2;
    const double dn   = (double)n;
    const double var  = (sd2t - sdt * sdt / dn) / (dn - 1.0);
    const float  c    = (float)(0.7071067811865476 / var);

    // ---------------- pass 2: sum (1 - erf(d*c)) from SMEM -------------------
    const long long mloc = bend - bstart;
    const long long m4   = mloc >> 2;
    float sp = 0.0f;
    for (long long i = tid; i < m4; i += NTHR) {
        h2x2 q = s4[i];
        float2 f0 = __half22float2(q.a);
        float2 f1 = __half22float2(q.b);
        sp += one_minus_erf(f0.x * c) + one_minus_erf(f0.y * c);
        sp += one_minus_erf(f1.x * c) + one_minus_erf(f1.y * c);
    }
    for (long long j = (m4 << 2) + tid; j < mloc; j += NTHR)
        sp += one_minus_erf(__half2float(s_d[j]) * c);

    block_reduce_1<NWARPS>(sp, &g_sum_p);

    // ---------------- phase-2 arrive; block 0 finalizes -----------------------
    __syncthreads();
    __threadfence();
    if (tid == 0) {
        if (bid != 0) {
            atomicAdd(&g_count, 1u);
        } else {
            const unsigned need = gridDim.x - 1;
            while (*((volatile unsigned*)&g_count) != need) { }
            g_count = 0;
            __threadfence();
            double mean_d = sdt / dn;
            float  p      = (float)(g_sum_p / dn);
            float  gamma  = -logf(p);
            float  pw     = expf(gamma * log1pf(-p));   // (1-p)^gamma
            out[0] = (float)mean_d * pw + log1pf((float)var);
            // reset accumulators for the next graph replay
            g_sum_d = 0.0; g_sum_d2 = 0.0; g_sum_p = 0.0;
        }
    }
}

// ============================ fallback path (large n) =======================
__global__ void afl_fb_pass1(const float* __restrict__ pred,
                             const float* __restrict__ target, long long n) {
    const long long n4 = n >> 2;
    const float4* __restrict__ p4 = (const float4*)pred;
    const float4* __restrict__ t4 = (const float4*)target;
    const long long stride = (long long)gridDim.x * blockDim.x;
    float sd = 0.0f, sd2 = 0.0f;
    for (long long i = (long long)blockIdx.x * blockDim.x + threadIdx.x; i < n4; i += stride) {
        float4 a = p4[i]; float4 b = t4[i];
        float d0 = fabsf(a.x - b.x), d1 = fabsf(a.y - b.y);
        float d2 = fabsf(a.z - b.z), d3 = fabsf(a.w - b.w);
        sd  += (d0 + d1) + (d2 + d3);
        sd2 += fmaf(d0, d0, d1 * d1) + fmaf(d2, d2, d3 * d3);
    }
    for (long long j = (n4 << 2) + (long long)blockIdx.x * blockDim.x + threadIdx.x;
         j < n; j += stride) {
        float d = fabsf(pred[j] - target[j]);
        sd += d; sd2 += d * d;
    }
    block_reduce_2<FB_WARPS>(sd, sd2, &g_sum_d, &g_sum_d2);
}

__global__ void afl_fb_pass2(const float* __restrict__ pred,
                             const float* __restrict__ target, long long n) {
    double sdt = g_sum_d, sd2t = g_sum_d2, dn = (double)n;
    double var = (sd2t - sdt * sdt / dn) / (dn - 1.0);
    float  c   = (float)(0.7071067811865476 / var);
    const long long n4 = n >> 2;
    const float4* __restrict__ p4 = (const float4*)pred;
    const float4* __restrict__ t4 = (const float4*)target;
    const long long stride = (long long)gridDim.x * blockDim.x;
    float sp = 0.0f;
    for (long long i = (long long)blockIdx.x * blockDim.x + threadIdx.x; i < n4; i += stride) {
        float4 a = p4[i]; float4 b = t4[i];
        sp += one_minus_erf(fabsf(a.x - b.x) * c) + one_minus_erf(fabsf(a.y - b.y) * c);
        sp += one_minus_erf(fabsf(a.z - b.z) * c) + one_minus_erf(fabsf(a.w - b.w) * c);
    }
    for (long long j = (n4 << 2) + (long long)blockIdx.x * blockDim.x + threadIdx.x;
         j < n; j += stride)
        sp += one_minus_erf(fabsf(pred[j] - target[j]) * c);
    block_reduce_1<FB_WARPS>(sp, &g_sum_p);
}

__global__ void afl_fb_finalize(float* __restrict__ out, long long n) {
    double dn = (double)n;
    double sdt = g_sum_d, sd2t = g_sum_d2;
    double mean_d = sdt / dn;
    double var = (sd2t - sdt * sdt / dn) / (dn - 1.0);
    float  p = (float)(g_sum_p / dn);
    float  gamma = -logf(p);
    float  pw = expf(gamma * log1pf(-p));
    out[0] = (float)mean_d * pw + log1pf((float)var);
    g_sum_d = 0.0; g_sum_d2 = 0.0; g_sum_p = 0.0;
}

// ================================ launcher ==================================
extern "C" void kernel_launch(void* const* d_in, const int* in_sizes, int n_in,
                              void* d_out, int out_size) {
    const float* pred   = (const float*)d_in[0];
    const float* target = (const float*)d_in[1];
    float* out = (float*)d_out;
    long long n = (long long)in_sizes[0];

    long long chunk = ((n + NBLK - 1) / NBLK + 3) & ~3LL;   // per-block elems, mult of 4
    size_t smem = (size_t)chunk * sizeof(__half);

    if (smem <= 227 * 1024) {
        // opt-in to large dynamic SMEM (host-side attribute set; not a stream op)
        cudaFuncSetAttribute(afl_fused_kernel,
                             cudaFuncAttributeMaxDynamicSharedMemorySize,
                             (int)smem);
        afl_fused_kernel<<<NBLK, NTHR, smem>>>(pred, target, out, n, chunk);
    } else {
        afl_fb_pass1<<<FB_BLOCKS, FB_THREADS>>>(pred, target, n);
        afl_fb_pass2<<<FB_BLOCKS, FB_THREADS>>>(pred, target, n);
        afl_fb_finalize<<<1, 1>>>(out, n);
    }
}